// round 15
// baseline (speedup 1.0000x reference)
#include <cuda_runtime.h>
#include <cuda_bf16.h>
#include <cstdint>

// PaiNN conv: ds (N,64), dv (N,3,64) concatenated in d_out.
// Inputs: 0 node(N,64) 1 equivariant(N,3,64) 2 rbf(E,20) 3 envelope(E,1)
//         4 r_ij(E,3) 5 edge_index(E,2) i64/i32  6 Ws(64,64) 7 bs(64)
//         8 Wphi(192,64) 9 bphi(192) 10 Ww(192,20) 11 bw(192)

#define U 64
#define S3 192
#define R 20
#define MAXN 50000
#define MAXE 800000
#define EROW 28          // floats per edge record (112B)
#define MT 64            // nodes per MLP tile
#define NGRP 1184        // sweep groups (64 thr) = 148 SM x 4 blk x 2 = 1 wave

typedef unsigned long long ull;

__device__ float g_s2[(size_t)MAXN * 256];   // packed [N][64][4]: (s0,s1,s2,-)
__device__ float g_v2[(size_t)MAXN * 256];   // packed [N][64][4]: (v0,v1,v2,-)
__device__ float g_edata[(size_t)MAXE * EROW];
__device__ int   g_idx_is64;
__device__ int   g_cnt[MAXN];
__device__ int   g_scan[MAXN];
__device__ int   g_bsum[64];
__device__ int   g_run[MAXN];

// ---------------- packed f32x2 helpers ----------------
__device__ __forceinline__ ull pk2(float lo, float hi) {
    ull r;
    asm("mov.b64 %0, {%1, %2};" : "=l"(r) : "f"(lo), "f"(hi));
    return r;
}
__device__ __forceinline__ ull fma2(ull a, ull b, ull c) {
    ull d;
    asm("fma.rn.f32x2 %0, %1, %2, %3;" : "=l"(d) : "l"(a), "l"(b), "l"(c));
    return d;
}
__device__ __forceinline__ void upk(ull a, float& lo, float& hi) {
    asm("mov.b64 {%0, %1}, %2;" : "=f"(lo), "=f"(hi) : "l"(a));
}
__device__ __forceinline__ float upk_sum(ull a) {
    float lo, hi;
    upk(a, lo, hi);
    return lo + hi;
}
__device__ __forceinline__ void red_add(float* p, float v) {
    asm volatile("red.global.add.f32 [%0], %1;" :: "l"(p), "f"(v) : "memory");
}

// ---------------- idx dtype detector + counter zero (fused) ----------------
__global__ void detect_zero_kernel(const int* __restrict__ eidx32,
                                   int n_edges, int n_nodes) {
    if (blockIdx.x == 0) {
        __shared__ int warp_or[8];
        int v = 0;
        int limit = n_edges < 4096 ? n_edges : 4096;
        for (int k = threadIdx.x; k < limit; k += blockDim.x)
            v |= eidx32[2 * k + 1];
        for (int o = 16; o > 0; o >>= 1)
            v |= __shfl_xor_sync(0xffffffffu, v, o);
        if ((threadIdx.x & 31) == 0) warp_or[threadIdx.x >> 5] = v;
        __syncthreads();
        if (threadIdx.x == 0) {
            int r = 0;
            for (int w = 0; w < (int)(blockDim.x >> 5); w++) r |= warp_or[w];
            g_idx_is64 = (r == 0) ? 1 : 0;
        }
    } else {
        int i = (blockIdx.x - 1) * blockDim.x + threadIdx.x;
        if (i < n_nodes) g_cnt[i] = 0;
    }
}

__global__ void zero_out_kernel(float* __restrict__ out, long long n) {
    long long n4 = n >> 2;
    float4 z = make_float4(0.f, 0.f, 0.f, 0.f);
    float4* o4 = (float4*)out;
    for (long long i = (long long)blockIdx.x * blockDim.x + threadIdx.x; i < n4;
         i += (long long)gridDim.x * blockDim.x)
        o4[i] = z;
    long long base = n4 << 2;
    for (long long i = base + (long long)blockIdx.x * blockDim.x + threadIdx.x; i < n;
         i += (long long)gridDim.x * blockDim.x)
        out[i] = 0.f;
}

// ---------------- pack equiv (N,3,64) -> g_v2 [N][64][4] ----------------
__global__ void pack_equiv_kernel(const float* __restrict__ equiv, int n_nodes) {
    int idx = blockIdx.x * blockDim.x + threadIdx.x;   // n*64 + ch
    if (idx < n_nodes * 64) {
        int n = idx >> 6, ch = idx & 63;
        const float* vp = equiv + (size_t)n * S3 + ch;
        float4 v = make_float4(vp[0], vp[64], vp[128], 0.f);
        ((float4*)g_v2)[idx] = v;
    }
}

__global__ void hist_kernel(const void* __restrict__ eidx, int n_edges) {
    const bool is64 = (g_idx_is64 != 0);
    for (int e = blockIdx.x * blockDim.x + threadIdx.x; e < n_edges;
         e += gridDim.x * blockDim.x) {
        int dst = is64 ? (int)((const long long*)eidx)[2 * (size_t)e]
                       : ((const int*)eidx)[2 * (size_t)e];
        atomicAdd(&g_cnt[dst], 1);
    }
}

__global__ void scan1_kernel(int n_nodes) {
    __shared__ int sh[1024];
    int tid = threadIdx.x;
    int i = blockIdx.x * 1024 + tid;
    int v = (i < n_nodes) ? g_cnt[i] : 0;
    sh[tid] = v;
    __syncthreads();
    for (int off = 1; off < 1024; off <<= 1) {
        int t = (tid >= off) ? sh[tid - off] : 0;
        __syncthreads();
        sh[tid] += t;
        __syncthreads();
    }
    if (i < n_nodes) g_scan[i] = sh[tid] - v;
    if (tid == 1023) g_bsum[blockIdx.x] = sh[1023];
}

// parallel block-sum exclusive scan (nb <= 64)
__global__ void scan2_kernel(int nb) {
    __shared__ int sh[64];
    int t = threadIdx.x;
    int v = (t < nb) ? g_bsum[t] : 0;
    sh[t] = v;
    __syncthreads();
    for (int off = 1; off < 64; off <<= 1) {
        int u = (t >= off) ? sh[t - off] : 0;
        __syncthreads();
        sh[t] += u;
        __syncthreads();
    }
    if (t < nb) g_bsum[t] = sh[t] - v;  // exclusive
}

__global__ void scan3_kernel(int n_nodes) {
    int i = blockIdx.x * blockDim.x + threadIdx.x;
    if (i < n_nodes)
        g_run[i] = g_scan[i] + g_bsum[i >> 10];
}

// ---------------- scatter: build 112B edge records in dst-sorted order ----
__global__ void scatter_kernel(const void* __restrict__ eidx,
                               const float* __restrict__ rbf,
                               const float* __restrict__ env,
                               const float* __restrict__ rij,
                               int n_edges) {
    const bool is64 = (g_idx_is64 != 0);
    for (int e = blockIdx.x * blockDim.x + threadIdx.x; e < n_edges;
         e += gridDim.x * blockDim.x) {
        int dst, j;
        if (is64) {
            const long long* p = (const long long*)eidx;
            dst = (int)p[2 * (size_t)e];
            j = (int)p[2 * (size_t)e + 1];
        } else {
            const int* p = (const int*)eidx;
            dst = p[2 * (size_t)e];
            j = p[2 * (size_t)e + 1];
        }
        int pos = atomicAdd(&g_run[dst], 1);
        float4* row = (float4*)(g_edata + (size_t)pos * EROW);
        float4 a;
        a.x = __int_as_float(j);
        a.y = __int_as_float(dst);
        a.z = env[e];
        a.w = 0.f;
        const float4* rb = (const float4*)(rbf + (size_t)e * R);
        float4 r0 = rb[0], r1 = rb[1], r2 = rb[2], r3 = rb[3], r4 = rb[4];
        float4 b;
        b.x = rij[3 * (size_t)e];
        b.y = rij[3 * (size_t)e + 1];
        b.z = rij[3 * (size_t)e + 2];
        b.w = 0.f;
        row[0] = a; row[1] = r0; row[2] = r1; row[3] = r2;
        row[4] = r3; row[5] = r4; row[6] = b;
    }
}

// ---------------- register-tiled node MLP -> packed g_s2 ----------------
#define SMEM_MLP ((64 * 68 + 64 * 196 + 192 + 64 * 66 + 64 * 66) * 4)

__global__ void __launch_bounds__(256)
mlp_kernel(const float* __restrict__ node,
           const float* __restrict__ Ws, const float* __restrict__ bs,
           const float* __restrict__ Wphi, const float* __restrict__ bphi,
           int n_nodes) {
    extern __shared__ float sh[];
    float* sWsT  = sh;
    float* sWpT  = sWsT + 64 * 68;
    float* sbphi = sWpT + 64 * 196;
    float* snT   = sbphi + 192;
    float* shhT  = snT + 64 * 66;

    const int tid = threadIdx.x;

    for (int x = tid; x < 64 * 64; x += 256) {
        int cc = x >> 6, k = x & 63;
        sWsT[k * 68 + cc] = Ws[x];
    }
    for (int x = tid; x < 192 * 64; x += 256) {
        int cc = x >> 6, k = x & 63;
        sWpT[k * 196 + cc] = Wphi[x];
    }
    for (int x = tid; x < 192; x += 256) sbphi[x] = bphi[x];

    const int n0 = blockIdx.x * MT;
    for (int x = tid; x < MT * 64; x += 256) {
        int n = x >> 6, k = x & 63;
        snT[k * 66 + n] = (n0 + n < n_nodes) ? node[(size_t)(n0 + n) * 64 + k] : 0.f;
    }
    __syncthreads();

    const int cq = tid & 15, nq = tid >> 4;
    const int cc0 = cq * 4, nn0 = nq * 4;

    {
        ull acc[4][2];
#pragma unroll
        for (int ci = 0; ci < 4; ci++) {
            float b = bs[cc0 + ci];
            acc[ci][0] = pk2(b, b);
            acc[ci][1] = pk2(b, b);
        }
#pragma unroll 8
        for (int k = 0; k < 64; k++) {
            float4 wv = *(const float4*)&sWsT[k * 68 + cc0];
            ull np0 = *(const ull*)&snT[k * 66 + nn0];
            ull np1 = *(const ull*)&snT[k * 66 + nn0 + 2];
            ull w;
            w = pk2(wv.x, wv.x); acc[0][0] = fma2(np0, w, acc[0][0]); acc[0][1] = fma2(np1, w, acc[0][1]);
            w = pk2(wv.y, wv.y); acc[1][0] = fma2(np0, w, acc[1][0]); acc[1][1] = fma2(np1, w, acc[1][1]);
            w = pk2(wv.z, wv.z); acc[2][0] = fma2(np0, w, acc[2][0]); acc[2][1] = fma2(np1, w, acc[2][1]);
            w = pk2(wv.w, wv.w); acc[3][0] = fma2(np0, w, acc[3][0]); acc[3][1] = fma2(np1, w, acc[3][1]);
        }
#pragma unroll
        for (int ci = 0; ci < 4; ci++) {
            float h0, h1, h2, h3;
            upk(acc[ci][0], h0, h1);
            upk(acc[ci][1], h2, h3);
            h0 *= 1.f / (1.f + __expf(-h0));
            h1 *= 1.f / (1.f + __expf(-h1));
            h2 *= 1.f / (1.f + __expf(-h2));
            h3 *= 1.f / (1.f + __expf(-h3));
            *(ull*)&shhT[(cc0 + ci) * 66 + nn0]     = pk2(h0, h1);
            *(ull*)&shhT[(cc0 + ci) * 66 + nn0 + 2] = pk2(h2, h3);
        }
    }
    __syncthreads();

    for (int p = 0; p < 3; p++) {
        ull acc[4][2];
#pragma unroll
        for (int ci = 0; ci < 4; ci++) {
            float b = sbphi[p * 64 + cc0 + ci];
            acc[ci][0] = pk2(b, b);
            acc[ci][1] = pk2(b, b);
        }
#pragma unroll 8
        for (int k = 0; k < 64; k++) {
            float4 wv = *(const float4*)&sWpT[k * 196 + p * 64 + cc0];
            ull np0 = *(const ull*)&shhT[k * 66 + nn0];
            ull np1 = *(const ull*)&shhT[k * 66 + nn0 + 2];
            ull w;
            w = pk2(wv.x, wv.x); acc[0][0] = fma2(np0, w, acc[0][0]); acc[0][1] = fma2(np1, w, acc[0][1]);
            w = pk2(wv.y, wv.y); acc[1][0] = fma2(np0, w, acc[1][0]); acc[1][1] = fma2(np1, w, acc[1][1]);
            w = pk2(wv.z, wv.z); acc[2][0] = fma2(np0, w, acc[2][0]); acc[2][1] = fma2(np1, w, acc[2][1]);
            w = pk2(wv.w, wv.w); acc[3][0] = fma2(np0, w, acc[3][0]); acc[3][1] = fma2(np1, w, acc[3][1]);
        }
        float sv[4][4];
#pragma unroll
        for (int ci = 0; ci < 4; ci++) {
            upk(acc[ci][0], sv[ci][0], sv[ci][1]);
            upk(acc[ci][1], sv[ci][2], sv[ci][3]);
        }
        // packed store: g_s2[n][ch][p]
#pragma unroll
        for (int ni = 0; ni < 4; ni++) {
            int n = n0 + nn0 + ni;
            if (n < n_nodes) {
#pragma unroll
                for (int ci = 0; ci < 4; ci++)
                    g_s2[(size_t)n * 256 + (cc0 + ci) * 4 + p] = sv[ci][ni];
            }
        }
    }
}

// ---------------- sweep: round-10 pipeline + single-LDG.128 gathers -------
// Group = 64 threads (2 warps) sweeping a contiguous dst-sorted range.
// Thread t owns radial channels {t,64+t,128+t} AND outputs ds[t],dv[*][t].
//   A: load header(pos+2)  (linear address, no deps)
//   B: 2 float4 gathers for pos+1 (packed tables; header loaded last iter)
//   C: compute pos (rbf/rij from record line — L1-hot)
__global__ void __launch_bounds__(128, 4)
sweep_kernel(const float* __restrict__ Ww, const float* __restrict__ bw,
             float* __restrict__ out_ds, float* __restrict__ out_dv,
             int n_edges) {
    const int grp = blockIdx.x * 2 + (threadIdx.x >> 6);   // group id
    const int t   = threadIdx.x & 63;                      // channel 0..63

    ull wwp[3][10];
    float bwv[3];
#pragma unroll
    for (int g = 0; g < 3; g++) {
        const float* wr = Ww + (size_t)(g * 64 + t) * R;
#pragma unroll
        for (int k = 0; k < 10; k++)
            wwp[g][k] = *(const ull*)&wr[2 * k];
        bwv[g] = bw[g * 64 + t];
    }

    const float4* s4 = (const float4*)g_s2;
    const float4* v4 = (const float4*)g_v2;

    const int begin = (int)(((long long)n_edges * grp) / NGRP);
    const int end   = (int)(((long long)n_edges * (grp + 1)) / NGRP);

    int   cur = -1;
    float a0 = 0.f, a1 = 0.f, a2 = 0.f, a3 = 0.f;

    // pipeline state
    int   niA = 0, niB = 0, jB = 0;
    float enA = 0.f, enB = 0.f;
    float4 sc = make_float4(0.f, 0.f, 0.f, 0.f);
    float4 vc = make_float4(0.f, 0.f, 0.f, 0.f);

    if (begin < end) {
        float4 h = *(const float4*)(g_edata + (size_t)begin * EROW);
        int jA = __float_as_int(h.x);
        niA = __float_as_int(h.y);
        enA = h.z;
        sc = s4[(size_t)jA * 64 + t];
        vc = v4[(size_t)jA * 64 + t];
        if (begin + 1 < end) {
            float4 h2 = *(const float4*)(g_edata + (size_t)(begin + 1) * EROW);
            jB  = __float_as_int(h2.x);
            niB = __float_as_int(h2.y);
            enB = h2.z;
        }
    }

    for (int pos = begin; pos < end; pos++) {
        // stage A: header(pos+2) — linear, independent, issues immediately
        int jC = 0, niC = 0;
        float enC = 0.f;
        if (pos + 2 < end) {
            float4 h = *(const float4*)(g_edata + (size_t)(pos + 2) * EROW);
            jC  = __float_as_int(h.x);
            niC = __float_as_int(h.y);
            enC = h.z;
        }

        // stage B: 2 packed gathers for pos+1
        float4 sn = make_float4(0.f, 0.f, 0.f, 0.f);
        float4 vn = make_float4(0.f, 0.f, 0.f, 0.f);
        if (pos + 1 < end) {
            sn = s4[(size_t)jB * 64 + t];
            vn = v4[(size_t)jB * 64 + t];
        }

        // stage C: compute pos (rbf/rij from record line — L1-hot)
        const float* row = g_edata + (size_t)pos * EROW;
        const ull* rb = (const ull*)(row + 4);
        float4 rj = *(const float4*)(row + 24);
        float w[3];
#pragma unroll
        for (int g = 0; g < 3; g++) {
            ull pa = pk2(bwv[g], 0.f);
            ull pb = pk2(0.f, 0.f);
#pragma unroll
            for (int q = 0; q < 5; q++) {
                pa = fma2(rb[2 * q],     wwp[g][2 * q],     pa);
                pb = fma2(rb[2 * q + 1], wwp[g][2 * q + 1], pb);
            }
            w[g] = (upk_sum(pa) + upk_sum(pb)) * enA;
        }

        float sw0 = sc.x * w[0];
        float sw1 = sc.y * w[1];
        float sw2 = sc.z * w[2];

        if (niA != cur) {
            if (cur >= 0) {
                red_add(out_ds + (size_t)cur * U + t, a0);
                float* dv = out_dv + (size_t)cur * S3 + t;
                red_add(dv,       a1);
                red_add(dv + 64,  a2);
                red_add(dv + 128, a3);
            }
            a0 = a1 = a2 = a3 = 0.f;
            cur = niA;
        }

        a0 += sw0;
        a1 = fmaf(vc.x, sw1, fmaf(rj.x, sw2, a1));
        a2 = fmaf(vc.y, sw1, fmaf(rj.y, sw2, a2));
        a3 = fmaf(vc.z, sw1, fmaf(rj.z, sw2, a3));

        // rotate pipeline state
        niA = niB; enA = enB;
        jB = jC; niB = niC; enB = enC;
        sc = sn; vc = vn;
    }

    if (cur >= 0) {
        red_add(out_ds + (size_t)cur * U + t, a0);
        float* dv = out_dv + (size_t)cur * S3 + t;
        red_add(dv,       a1);
        red_add(dv + 64,  a2);
        red_add(dv + 128, a3);
    }
}

// ---------------------------------------------------------------------------
extern "C" void kernel_launch(void* const* d_in, const int* in_sizes, int n_in,
                              void* d_out, int out_size) {
    const float* node  = (const float*)d_in[0];
    const float* equiv = (const float*)d_in[1];
    const float* rbf   = (const float*)d_in[2];
    const float* env   = (const float*)d_in[3];
    const float* rij   = (const float*)d_in[4];
    const void*  eidx  = d_in[5];
    const float* Ws    = (const float*)d_in[6];
    const float* bs    = (const float*)d_in[7];
    const float* Wphi  = (const float*)d_in[8];
    const float* bphi  = (const float*)d_in[9];
    const float* Ww    = (const float*)d_in[10];
    const float* bw    = (const float*)d_in[11];

    int n_nodes = in_sizes[0] / U;
    int n_edges = in_sizes[3];

    float* out_ds = (float*)d_out;
    float* out_dv = out_ds + (size_t)n_nodes * U;

    int nb_scan = (n_nodes + 1023) / 1024;

    detect_zero_kernel<<<1 + (n_nodes + 255) / 256, 256>>>((const int*)eidx,
                                                           n_edges, n_nodes);
    zero_out_kernel<<<592, 256>>>((float*)d_out, (long long)out_size);

    cudaFuncSetAttribute(mlp_kernel, cudaFuncAttributeMaxDynamicSharedMemorySize, SMEM_MLP);
    mlp_kernel<<<(n_nodes + MT - 1) / MT, 256, SMEM_MLP>>>(node, Ws, bs, Wphi, bphi, n_nodes);

    pack_equiv_kernel<<<(n_nodes * 64 + 255) / 256, 256>>>(equiv, n_nodes);

    hist_kernel<<<400, 256>>>(eidx, n_edges);
    scan1_kernel<<<nb_scan, 1024>>>(n_nodes);
    scan2_kernel<<<1, 64>>>(nb_scan);
    scan3_kernel<<<(n_nodes + 1023) / 1024, 1024>>>(n_nodes);
    scatter_kernel<<<400, 256>>>(eidx, rbf, env, rij, n_edges);

    sweep_kernel<<<NGRP / 2, 128>>>(Ww, bw, out_ds, out_dv, n_edges);
}

// round 16
// speedup vs baseline: 1.4127x; 1.4127x over previous
#include <cuda_runtime.h>
#include <cuda_fp16.h>
#include <cstdint>

// PaiNN conv: ds (N,64), dv (N,3,64) concatenated in d_out.
// Inputs: 0 node(N,64) 1 equivariant(N,3,64) 2 rbf(E,20) 3 envelope(E,1)
//         4 r_ij(E,3) 5 edge_index(E,2) i64/i32  6 Ws(64,64) 7 bs(64)
//         8 Wphi(192,64) 9 bphi(192) 10 Ww(192,20) 11 bw(192)

#define U 64
#define S3 192
#define R 20
#define MAXN 50000
#define MAXE 800000
#define EROW 28          // floats per edge record (112B)
#define MT 64            // nodes per MLP tile
#define NGRP 1184        // sweep groups (64 thr) = 148 SM x 4 blk x 2 = 1 wave

typedef unsigned long long ull;

__device__ float g_s[(size_t)MAXN * S3];
__device__ ull   g_p8[(size_t)MAXN * 64];    // fp16x4: (s0,s1 | s2,v0)
__device__ unsigned g_p4[(size_t)MAXN * 64]; // fp16x2: (v1,v2)
__device__ float g_edata[(size_t)MAXE * EROW];
__device__ int   g_idx_is64;
__device__ int   g_cnt[MAXN];
__device__ int   g_scan[MAXN];
__device__ int   g_bsum[64];
__device__ int   g_run[MAXN];

// ---------------- packed f32x2 helpers ----------------
__device__ __forceinline__ ull pk2(float lo, float hi) {
    ull r;
    asm("mov.b64 %0, {%1, %2};" : "=l"(r) : "f"(lo), "f"(hi));
    return r;
}
__device__ __forceinline__ ull fma2(ull a, ull b, ull c) {
    ull d;
    asm("fma.rn.f32x2 %0, %1, %2, %3;" : "=l"(d) : "l"(a), "l"(b), "l"(c));
    return d;
}
__device__ __forceinline__ void upk(ull a, float& lo, float& hi) {
    asm("mov.b64 {%0, %1}, %2;" : "=f"(lo), "=f"(hi) : "l"(a));
}
__device__ __forceinline__ float upk_sum(ull a) {
    float lo, hi;
    upk(a, lo, hi);
    return lo + hi;
}
__device__ __forceinline__ void red_add(float* p, float v) {
    asm volatile("red.global.add.f32 [%0], %1;" :: "l"(p), "f"(v) : "memory");
}

// ---------------- idx dtype detector + counter zero (fused) ----------------
__global__ void detect_zero_kernel(const int* __restrict__ eidx32,
                                   int n_edges, int n_nodes) {
    if (blockIdx.x == 0) {
        __shared__ int warp_or[8];
        int v = 0;
        int limit = n_edges < 4096 ? n_edges : 4096;
        for (int k = threadIdx.x; k < limit; k += blockDim.x)
            v |= eidx32[2 * k + 1];
        for (int o = 16; o > 0; o >>= 1)
            v |= __shfl_xor_sync(0xffffffffu, v, o);
        if ((threadIdx.x & 31) == 0) warp_or[threadIdx.x >> 5] = v;
        __syncthreads();
        if (threadIdx.x == 0) {
            int r = 0;
            for (int w = 0; w < (int)(blockDim.x >> 5); w++) r |= warp_or[w];
            g_idx_is64 = (r == 0) ? 1 : 0;
        }
    } else {
        int i = (blockIdx.x - 1) * blockDim.x + threadIdx.x;
        if (i < n_nodes) g_cnt[i] = 0;
    }
}

__global__ void zero_out_kernel(float* __restrict__ out, long long n) {
    long long n4 = n >> 2;
    float4 z = make_float4(0.f, 0.f, 0.f, 0.f);
    float4* o4 = (float4*)out;
    for (long long i = (long long)blockIdx.x * blockDim.x + threadIdx.x; i < n4;
         i += (long long)gridDim.x * blockDim.x)
        o4[i] = z;
    long long base = n4 << 2;
    for (long long i = base + (long long)blockIdx.x * blockDim.x + threadIdx.x; i < n;
         i += (long long)gridDim.x * blockDim.x)
        out[i] = 0.f;
}

// ---------------- pack s + equiv into fp16 tables ----------------
__global__ void pack_sv_kernel(const float* __restrict__ equiv, int n_nodes) {
    int idx = blockIdx.x * blockDim.x + threadIdx.x;   // n*64 + ch
    if (idx < n_nodes * 64) {
        int n = idx >> 6, ch = idx & 63;
        const float* sp = g_s + (size_t)n * S3 + ch;
        float s0 = sp[0], s1 = sp[64], s2 = sp[128];
        const float* vp = equiv + (size_t)n * S3 + ch;
        float v0 = vp[0], v1 = vp[64], v2 = vp[128];
        __half2 h01 = __floats2half2_rn(s0, s1);
        __half2 h23 = __floats2half2_rn(s2, v0);
        __half2 h45 = __floats2half2_rn(v1, v2);
        unsigned lo = *reinterpret_cast<unsigned*>(&h01);
        unsigned hi = *reinterpret_cast<unsigned*>(&h23);
        g_p8[idx] = ((ull)hi << 32) | lo;
        g_p4[idx] = *reinterpret_cast<unsigned*>(&h45);
    }
}

__global__ void hist_kernel(const void* __restrict__ eidx, int n_edges) {
    const bool is64 = (g_idx_is64 != 0);
    for (int e = blockIdx.x * blockDim.x + threadIdx.x; e < n_edges;
         e += gridDim.x * blockDim.x) {
        int dst = is64 ? (int)((const long long*)eidx)[2 * (size_t)e]
                       : ((const int*)eidx)[2 * (size_t)e];
        atomicAdd(&g_cnt[dst], 1);
    }
}

__global__ void scan1_kernel(int n_nodes) {
    __shared__ int sh[1024];
    int tid = threadIdx.x;
    int i = blockIdx.x * 1024 + tid;
    int v = (i < n_nodes) ? g_cnt[i] : 0;
    sh[tid] = v;
    __syncthreads();
    for (int off = 1; off < 1024; off <<= 1) {
        int t = (tid >= off) ? sh[tid - off] : 0;
        __syncthreads();
        sh[tid] += t;
        __syncthreads();
    }
    if (i < n_nodes) g_scan[i] = sh[tid] - v;
    if (tid == 1023) g_bsum[blockIdx.x] = sh[1023];
}

// parallel block-sum exclusive scan (nb <= 64)
__global__ void scan2_kernel(int nb) {
    __shared__ int sh[64];
    int t = threadIdx.x;
    int v = (t < nb) ? g_bsum[t] : 0;
    sh[t] = v;
    __syncthreads();
    for (int off = 1; off < 64; off <<= 1) {
        int u = (t >= off) ? sh[t - off] : 0;
        __syncthreads();
        sh[t] += u;
        __syncthreads();
    }
    if (t < nb) g_bsum[t] = sh[t] - v;  // exclusive
}

__global__ void scan3_kernel(int n_nodes) {
    int i = blockIdx.x * blockDim.x + threadIdx.x;
    if (i < n_nodes)
        g_run[i] = g_scan[i] + g_bsum[i >> 10];
}

// ---------------- scatter: build 112B edge records in dst-sorted order ----
__global__ void scatter_kernel(const void* __restrict__ eidx,
                               const float* __restrict__ rbf,
                               const float* __restrict__ env,
                               const float* __restrict__ rij,
                               int n_edges) {
    const bool is64 = (g_idx_is64 != 0);
    for (int e = blockIdx.x * blockDim.x + threadIdx.x; e < n_edges;
         e += gridDim.x * blockDim.x) {
        int dst, j;
        if (is64) {
            const long long* p = (const long long*)eidx;
            dst = (int)p[2 * (size_t)e];
            j = (int)p[2 * (size_t)e + 1];
        } else {
            const int* p = (const int*)eidx;
            dst = p[2 * (size_t)e];
            j = p[2 * (size_t)e + 1];
        }
        int pos = atomicAdd(&g_run[dst], 1);
        float4* row = (float4*)(g_edata + (size_t)pos * EROW);
        float4 a;
        a.x = __int_as_float(j);
        a.y = __int_as_float(dst);
        a.z = env[e];
        a.w = 0.f;
        const float4* rb = (const float4*)(rbf + (size_t)e * R);
        float4 r0 = rb[0], r1 = rb[1], r2 = rb[2], r3 = rb[3], r4 = rb[4];
        float4 b;
        b.x = rij[3 * (size_t)e];
        b.y = rij[3 * (size_t)e + 1];
        b.z = rij[3 * (size_t)e + 2];
        b.w = 0.f;
        row[0] = a; row[1] = r0; row[2] = r1; row[3] = r2;
        row[4] = r3; row[5] = r4; row[6] = b;
    }
}

// ---------------- register-tiled node MLP (proven: 89us) ----------------
#define SMEM_MLP ((64 * 68 + 64 * 196 + 192 + 64 * 66 + 64 * 66) * 4)

__global__ void __launch_bounds__(256)
mlp_kernel(const float* __restrict__ node,
           const float* __restrict__ Ws, const float* __restrict__ bs,
           const float* __restrict__ Wphi, const float* __restrict__ bphi,
           int n_nodes) {
    extern __shared__ float sh[];
    float* sWsT  = sh;
    float* sWpT  = sWsT + 64 * 68;
    float* sbphi = sWpT + 64 * 196;
    float* snT   = sbphi + 192;
    float* shhT  = snT + 64 * 66;

    const int tid = threadIdx.x;

    for (int x = tid; x < 64 * 64; x += 256) {
        int cc = x >> 6, k = x & 63;
        sWsT[k * 68 + cc] = Ws[x];
    }
    for (int x = tid; x < 192 * 64; x += 256) {
        int cc = x >> 6, k = x & 63;
        sWpT[k * 196 + cc] = Wphi[x];
    }
    for (int x = tid; x < 192; x += 256) sbphi[x] = bphi[x];

    const int n0 = blockIdx.x * MT;
    for (int x = tid; x < MT * 64; x += 256) {
        int n = x >> 6, k = x & 63;
        snT[k * 66 + n] = (n0 + n < n_nodes) ? node[(size_t)(n0 + n) * 64 + k] : 0.f;
    }
    __syncthreads();

    const int cq = tid & 15, nq = tid >> 4;
    const int cc0 = cq * 4, nn0 = nq * 4;

    {
        ull acc[4][2];
#pragma unroll
        for (int ci = 0; ci < 4; ci++) {
            float b = bs[cc0 + ci];
            acc[ci][0] = pk2(b, b);
            acc[ci][1] = pk2(b, b);
        }
#pragma unroll 8
        for (int k = 0; k < 64; k++) {
            float4 wv = *(const float4*)&sWsT[k * 68 + cc0];
            ull np0 = *(const ull*)&snT[k * 66 + nn0];
            ull np1 = *(const ull*)&snT[k * 66 + nn0 + 2];
            ull w;
            w = pk2(wv.x, wv.x); acc[0][0] = fma2(np0, w, acc[0][0]); acc[0][1] = fma2(np1, w, acc[0][1]);
            w = pk2(wv.y, wv.y); acc[1][0] = fma2(np0, w, acc[1][0]); acc[1][1] = fma2(np1, w, acc[1][1]);
            w = pk2(wv.z, wv.z); acc[2][0] = fma2(np0, w, acc[2][0]); acc[2][1] = fma2(np1, w, acc[2][1]);
            w = pk2(wv.w, wv.w); acc[3][0] = fma2(np0, w, acc[3][0]); acc[3][1] = fma2(np1, w, acc[3][1]);
        }
#pragma unroll
        for (int ci = 0; ci < 4; ci++) {
            float h0, h1, h2, h3;
            upk(acc[ci][0], h0, h1);
            upk(acc[ci][1], h2, h3);
            h0 *= 1.f / (1.f + __expf(-h0));
            h1 *= 1.f / (1.f + __expf(-h1));
            h2 *= 1.f / (1.f + __expf(-h2));
            h3 *= 1.f / (1.f + __expf(-h3));
            *(ull*)&shhT[(cc0 + ci) * 66 + nn0]     = pk2(h0, h1);
            *(ull*)&shhT[(cc0 + ci) * 66 + nn0 + 2] = pk2(h2, h3);
        }
    }
    __syncthreads();

    for (int p = 0; p < 3; p++) {
        ull acc[4][2];
#pragma unroll
        for (int ci = 0; ci < 4; ci++) {
            float b = sbphi[p * 64 + cc0 + ci];
            acc[ci][0] = pk2(b, b);
            acc[ci][1] = pk2(b, b);
        }
#pragma unroll 8
        for (int k = 0; k < 64; k++) {
            float4 wv = *(const float4*)&sWpT[k * 196 + p * 64 + cc0];
            ull np0 = *(const ull*)&shhT[k * 66 + nn0];
            ull np1 = *(const ull*)&shhT[k * 66 + nn0 + 2];
            ull w;
            w = pk2(wv.x, wv.x); acc[0][0] = fma2(np0, w, acc[0][0]); acc[0][1] = fma2(np1, w, acc[0][1]);
            w = pk2(wv.y, wv.y); acc[1][0] = fma2(np0, w, acc[1][0]); acc[1][1] = fma2(np1, w, acc[1][1]);
            w = pk2(wv.z, wv.z); acc[2][0] = fma2(np0, w, acc[2][0]); acc[2][1] = fma2(np1, w, acc[2][1]);
            w = pk2(wv.w, wv.w); acc[3][0] = fma2(np0, w, acc[3][0]); acc[3][1] = fma2(np1, w, acc[3][1]);
        }
        float sv[4][4];
#pragma unroll
        for (int ci = 0; ci < 4; ci++) {
            upk(acc[ci][0], sv[ci][0], sv[ci][1]);
            upk(acc[ci][1], sv[ci][2], sv[ci][3]);
        }
#pragma unroll
        for (int ni = 0; ni < 4; ni++) {
            int n = n0 + nn0 + ni;
            if (n < n_nodes) {
                float4 v = make_float4(sv[0][ni], sv[1][ni], sv[2][ni], sv[3][ni]);
                *(float4*)&g_s[(size_t)n * S3 + p * 64 + cc0] = v;
            }
        }
    }
}

// ---------------- sweep: round-10 pipeline + fp16-packed gathers ----------
// Group = 64 threads (2 warps) sweeping a contiguous dst-sorted range.
// Thread t owns radial channels {t,64+t,128+t} AND outputs ds[t],dv[*][t].
//   A: load header(pos+2)  (linear address, no deps)
//   B: 2 packed-fp16 gathers for pos+1 (768B/edge total, half of f32)
//   C: compute pos (rbf/rij from record line — L1-hot; accum fp32)
__global__ void __launch_bounds__(128, 4)
sweep_kernel(const float* __restrict__ Ww, const float* __restrict__ bw,
             float* __restrict__ out_ds, float* __restrict__ out_dv,
             int n_edges) {
    const int grp = blockIdx.x * 2 + (threadIdx.x >> 6);   // group id
    const int t   = threadIdx.x & 63;                      // channel 0..63

    ull wwp[3][10];
    float bwv[3];
#pragma unroll
    for (int g = 0; g < 3; g++) {
        const float* wr = Ww + (size_t)(g * 64 + t) * R;
#pragma unroll
        for (int k = 0; k < 10; k++)
            wwp[g][k] = *(const ull*)&wr[2 * k];
        bwv[g] = bw[g * 64 + t];
    }

    const int begin = (int)(((long long)n_edges * grp) / NGRP);
    const int end   = (int)(((long long)n_edges * (grp + 1)) / NGRP);

    int   cur = -1;
    float a0 = 0.f, a1 = 0.f, a2 = 0.f, a3 = 0.f;

    // pipeline state
    int   niA = 0, niB = 0, jB = 0;
    float enA = 0.f, enB = 0.f;
    ull      p8 = 0;
    unsigned p4 = 0;

    if (begin < end) {
        float4 h = *(const float4*)(g_edata + (size_t)begin * EROW);
        int jA = __float_as_int(h.x);
        niA = __float_as_int(h.y);
        enA = h.z;
        p8 = g_p8[(size_t)jA * 64 + t];
        p4 = g_p4[(size_t)jA * 64 + t];
        if (begin + 1 < end) {
            float4 h2 = *(const float4*)(g_edata + (size_t)(begin + 1) * EROW);
            jB  = __float_as_int(h2.x);
            niB = __float_as_int(h2.y);
            enB = h2.z;
        }
    }

    for (int pos = begin; pos < end; pos++) {
        // stage A: header(pos+2) — linear, independent, issues immediately
        int jC = 0, niC = 0;
        float enC = 0.f;
        if (pos + 2 < end) {
            float4 h = *(const float4*)(g_edata + (size_t)(pos + 2) * EROW);
            jC  = __float_as_int(h.x);
            niC = __float_as_int(h.y);
            enC = h.z;
        }

        // stage B: 2 packed gathers for pos+1
        ull      p8n = 0;
        unsigned p4n = 0;
        if (pos + 1 < end) {
            p8n = g_p8[(size_t)jB * 64 + t];
            p4n = g_p4[(size_t)jB * 64 + t];
        }

        // stage C: compute pos (rbf/rij from record line — L1-hot)
        const float* row = g_edata + (size_t)pos * EROW;
        const ull* rb = (const ull*)(row + 4);
        float4 rj = *(const float4*)(row + 24);
        float w[3];
#pragma unroll
        for (int g = 0; g < 3; g++) {
            ull pa = pk2(bwv[g], 0.f);
            ull pb = pk2(0.f, 0.f);
#pragma unroll
            for (int q = 0; q < 5; q++) {
                pa = fma2(rb[2 * q],     wwp[g][2 * q],     pa);
                pb = fma2(rb[2 * q + 1], wwp[g][2 * q + 1], pb);
            }
            w[g] = (upk_sum(pa) + upk_sum(pb)) * enA;
        }

        // unpack fp16 gather values
        unsigned lo = (unsigned)p8;
        unsigned hi = (unsigned)(p8 >> 32);
        float2 f01 = __half22float2(*reinterpret_cast<__half2*>(&lo));
        float2 f23 = __half22float2(*reinterpret_cast<__half2*>(&hi));
        float2 f45 = __half22float2(*reinterpret_cast<__half2*>(&p4));
        // f01 = (s0, s1), f23 = (s2, v0), f45 = (v1, v2)

        float sw0 = f01.x * w[0];
        float sw1 = f01.y * w[1];
        float sw2 = f23.x * w[2];

        if (niA != cur) {
            if (cur >= 0) {
                red_add(out_ds + (size_t)cur * U + t, a0);
                float* dv = out_dv + (size_t)cur * S3 + t;
                red_add(dv,       a1);
                red_add(dv + 64,  a2);
                red_add(dv + 128, a3);
            }
            a0 = a1 = a2 = a3 = 0.f;
            cur = niA;
        }

        a0 += sw0;
        a1 = fmaf(f23.y, sw1, fmaf(rj.x, sw2, a1));
        a2 = fmaf(f45.x, sw1, fmaf(rj.y, sw2, a2));
        a3 = fmaf(f45.y, sw1, fmaf(rj.z, sw2, a3));

        // rotate pipeline state
        niA = niB; enA = enB;
        jB = jC; niB = niC; enB = enC;
        p8 = p8n; p4 = p4n;
    }

    if (cur >= 0) {
        red_add(out_ds + (size_t)cur * U + t, a0);
        float* dv = out_dv + (size_t)cur * S3 + t;
        red_add(dv,       a1);
        red_add(dv + 64,  a2);
        red_add(dv + 128, a3);
    }
}

// ---------------------------------------------------------------------------
extern "C" void kernel_launch(void* const* d_in, const int* in_sizes, int n_in,
                              void* d_out, int out_size) {
    const float* node  = (const float*)d_in[0];
    const float* equiv = (const float*)d_in[1];
    const float* rbf   = (const float*)d_in[2];
    const float* env   = (const float*)d_in[3];
    const float* rij   = (const float*)d_in[4];
    const void*  eidx  = d_in[5];
    const float* Ws    = (const float*)d_in[6];
    const float* bs    = (const float*)d_in[7];
    const float* Wphi  = (const float*)d_in[8];
    const float* bphi  = (const float*)d_in[9];
    const float* Ww    = (const float*)d_in[10];
    const float* bw    = (const float*)d_in[11];

    int n_nodes = in_sizes[0] / U;
    int n_edges = in_sizes[3];

    float* out_ds = (float*)d_out;
    float* out_dv = out_ds + (size_t)n_nodes * U;

    int nb_scan = (n_nodes + 1023) / 1024;

    detect_zero_kernel<<<1 + (n_nodes + 255) / 256, 256>>>((const int*)eidx,
                                                           n_edges, n_nodes);
    zero_out_kernel<<<592, 256>>>((float*)d_out, (long long)out_size);

    cudaFuncSetAttribute(mlp_kernel, cudaFuncAttributeMaxDynamicSharedMemorySize, SMEM_MLP);
    mlp_kernel<<<(n_nodes + MT - 1) / MT, 256, SMEM_MLP>>>(node, Ws, bs, Wphi, bphi, n_nodes);

    pack_sv_kernel<<<(n_nodes * 64 + 255) / 256, 256>>>(equiv, n_nodes);

    hist_kernel<<<400, 256>>>(eidx, n_edges);
    scan1_kernel<<<nb_scan, 1024>>>(n_nodes);
    scan2_kernel<<<1, 64>>>(nb_scan);
    scan3_kernel<<<(n_nodes + 1023) / 1024, 1024>>>(n_nodes);
    scatter_kernel<<<400, 256>>>(eidx, rbf, env, rij, n_edges);

    sweep_kernel<<<NGRP / 2, 128>>>(Ww, bw, out_ds, out_dv, n_edges);
}